// round 2
// baseline (speedup 1.0000x reference)
#include <cuda_runtime.h>
#include <math.h>

// CustomLSTM: 2-layer LSTM, B=128, T=512, IN=64, H=1024, OUT=1
// Round 2: persistent kernel (4 graph nodes total) + software grid barrier.
// fp32 SIMT GEMM with packed fma.rn.f32x2, cell state register-resident.

#define Bb    128
#define Tt    512
#define INP   64
#define Hh    1024
#define G4    4096
#define NBLK  128
#define NTHR  256
#define KTILE 64

typedef unsigned long long ull;

// ---------------- device scratch (no allocations allowed) ----------------
__device__ float d_h0T[2][Hh * Bb];   // layer0 hidden, double buffered, [j][b]
__device__ float d_h1T[2][Hh * Bb];   // layer1 hidden, double buffered
__device__ float d_bi0[Bb * Hh];      // boundary -> forget-gate extra, [b][j]
__device__ float d_bi1[Bb * Hh];
__device__ float d_bias0[G4];         // bx0 + bh0
__device__ float d_bias1[G4];         // bx1 + bh1
__device__ float d_xT[Tt * INP * Bb]; // x transposed to [t][kin][b]
__device__ unsigned int g_count;      // grid barrier arrive counter
__device__ volatile unsigned int g_gen; // grid barrier generation

// ---------------- setup: zero state, fold biases, boundary terms ----------------
__global__ void setup_kernel(const float* __restrict__ boundary,
                             const float* __restrict__ bx0, const float* __restrict__ bh0,
                             const float* __restrict__ bb0, const float* __restrict__ Wb0,
                             const float* __restrict__ bx1, const float* __restrict__ bh1,
                             const float* __restrict__ bb1, const float* __restrict__ Wb1)
{
    int idx = blockIdx.x * 256 + threadIdx.x;   // grid covers B*H = 131072
    if (idx == 0) { g_count = 0; g_gen = 0; }   // reset barrier state EVERY launch
    d_h0T[0][idx] = 0.f;
    d_h1T[0][idx] = 0.f;
    int b = idx >> 10;          // batch
    int j = idx & 1023;         // hidden unit
    float p0 = boundary[b * 2 + 0];
    float p1 = boundary[b * 2 + 1];
    d_bi0[idx] = p0 * Wb0[j * 2 + 0] + p1 * Wb0[j * 2 + 1] + bb0[j];
    d_bi1[idx] = p0 * Wb1[j * 2 + 0] + p1 * Wb1[j * 2 + 1] + bb1[j];
    if (idx < G4) {
        d_bias0[idx] = bx0[idx] + bh0[idx];
        d_bias1[idx] = bx1[idx] + bh1[idx];
    }
}

// x: [B][T][IN] -> d_xT: [t][kin][b]
__global__ void transpose_kernel(const float* __restrict__ x)
{
    int idx = blockIdx.x * 256 + threadIdx.x;   // grid covers T*IN*B
    int b   = idx & 127;
    int kin = (idx >> 7) & 63;
    int t   = idx >> 13;
    d_xT[idx] = x[b * (Tt * INP) + t * INP + kin];
}

// ---------------- fast activations (accurate ~1e-7, safe at extremes) ----------------
__device__ __forceinline__ float sigf(float x)
{
    return __fdividef(1.f, 1.f + __expf(-x));
}
__device__ __forceinline__ float tanh_f(float x)
{
    float xc = fminf(fmaxf(x, -15.f), 15.f);
    float e  = __expf(-2.f * xc);               // in [e^-30, e^30], finite
    return (1.f - e) * __fdividef(1.f, 1.f + e);
}

// ---------------- grid-wide barrier (all 128 blocks co-resident) ----------------
__device__ __forceinline__ void grid_barrier(unsigned target)
{
    __syncthreads();
    if (threadIdx.x == 0) {
        __threadfence();
        unsigned old = atomicAdd(&g_count, 1u);
        if (old == NBLK - 1) {
            g_count = 0;
            __threadfence();
            g_gen = target;                      // release
        } else {
            while (g_gen < target) __nanosleep(64);
        }
    }
    __syncthreads();
}

// ---------------- one layer, one timestep: fused GEMM + LSTM cell ----------------
// gates[32 rows x 128 b] = A1[K1 x B] part + A2[K2 x B] part (weights row-major, ld = K)
// Block covers 8 hidden units (x4 gates). Thread = (unit u of 8, 4 batches).
__device__ __forceinline__ void layer_step(
    const float* __restrict__ A1, const float* __restrict__ A2,
    const float* __restrict__ W1, int ldw1, int K1,
    const float* __restrict__ W2, int ldw2, int K2,
    float* __restrict__ hout,
    float c[4], const float bg4[4], const float bif[4],
    float (*sA)[Bb], ull (*sW)[32])
{
    const int tid = threadIdx.x;
    const int u   = tid & 7;
    const int b0  = (tid >> 3) * 4;
    const int j0  = blockIdx.x * 8;
    const int j   = j0 + u;

    ull acc[4][2];
#pragma unroll
    for (int g = 0; g < 4; ++g) { acc[g][0] = 0ull; acc[g][1] = 0ull; }

    const int KT = K1 + K2;
    for (int k0 = 0; k0 < KT; k0 += KTILE) {
        const float* Asrc; const float* Wsrc; int ld; int kk;
        if (k0 < K1) { Asrc = A1; Wsrc = W1; ld = ldw1; kk = k0; }
        else         { Asrc = A2; Wsrc = W2; ld = ldw2; kk = k0 - K1; }

        // A tile: KTILE x 128 floats, coalesced float4 via L2 (bypass L1: cross-SM state)
        {
            const float4* s4 = reinterpret_cast<const float4*>(Asrc + kk * Bb);
            float4* dst4 = reinterpret_cast<float4*>(&sA[0][0]);
#pragma unroll
            for (int i = 0; i < (KTILE * 32) / NTHR; ++i)
                dst4[tid + i * NTHR] = __ldcg(&s4[tid + i * NTHR]);
        }
        // W tile: 32 rows x KTILE k, duplicated into f32x2 pairs
#pragma unroll
        for (int i = 0; i < (KTILE * 32) / NTHR; ++i) {
            int flat = tid + i * NTHR;
            int k    = flat & (KTILE - 1);
            int r    = flat / KTILE;                 // 0..31 = gate*8 + unit
            int row  = (r >> 3) * Hh + j0 + (r & 7);
            float w  = Wsrc[row * ld + kk + k];
            ull wp;  asm("mov.b64 %0, {%1, %1};" : "=l"(wp) : "f"(w));
            sW[k][r] = wp;
        }
        __syncthreads();

#pragma unroll 8
        for (int k = 0; k < KTILE; ++k) {
            const ull* ar = reinterpret_cast<const ull*>(&sA[k][b0]);
            ull a0 = ar[0], a1 = ar[1];
#pragma unroll
            for (int g = 0; g < 4; ++g) {
                ull w = sW[k][g * 8 + u];
                asm("fma.rn.f32x2 %0, %1, %2, %0;" : "+l"(acc[g][0]) : "l"(a0), "l"(w));
                asm("fma.rn.f32x2 %0, %1, %2, %0;" : "+l"(acc[g][1]) : "l"(a1), "l"(w));
            }
        }
        __syncthreads();
    }

    // unpack accumulators and run the cell for 4 (j, b) pairs
    float gv[4][4];
#pragma unroll
    for (int g = 0; g < 4; ++g) {
#pragma unroll
        for (int p = 0; p < 2; ++p)
            asm("mov.b64 {%0, %1}, %2;"
                : "=f"(gv[g][2 * p]), "=f"(gv[g][2 * p + 1]) : "l"(acc[g][p]));
    }
#pragma unroll
    for (int p = 0; p < 4; ++p) {
        float pi = gv[0][p] + bg4[0];
        float pf = gv[1][p] + bg4[1] + bif[p];
        float po = gv[2][p] + bg4[2];
        float pg = gv[3][p] + bg4[3];
        float iv = sigf(pi);
        float fv = sigf(pf);
        float ov = sigf(po);
        float gg = tanh_f(pg);
        float cn = fv * c[p] + iv * gg;
        c[p] = cn;
        hout[j * Bb + b0 + p] = ov * tanh_f(cn);
    }
}

// ---------------- persistent kernel: all 512 steps, both layers ----------------
__global__ void __launch_bounds__(NTHR, 1) lstm_persistent(
    const float* __restrict__ Uh0, const float* __restrict__ Wx0,
    const float* __restrict__ Wx1, const float* __restrict__ Uh1)
{
    __shared__ __align__(16) float sA[KTILE][Bb];  // 32 KB
    __shared__ ull sW[KTILE][32];                  // 16 KB  (total = 48 KB exactly)

    const int tid = threadIdx.x;
    const int u   = tid & 7;
    const int b0  = (tid >> 3) * 4;
    const int j   = blockIdx.x * 8 + u;

    // preload biases / boundary terms into registers (live for whole kernel)
    float bg0[4], bg1[4], bif0[4], bif1[4];
#pragma unroll
    for (int g = 0; g < 4; ++g) {
        bg0[g] = d_bias0[g * Hh + j];
        bg1[g] = d_bias1[g * Hh + j];
    }
#pragma unroll
    for (int p = 0; p < 4; ++p) {
        bif0[p] = d_bi0[(b0 + p) * Hh + j];
        bif1[p] = d_bi1[(b0 + p) * Hh + j];
    }
    float c0[4] = {0.f, 0.f, 0.f, 0.f};
    float c1[4] = {0.f, 0.f, 0.f, 0.f};

    for (int t = 0; t < Tt; ++t) {
        const int rd = t & 1;
        const int wr = 1 - rd;
        // layer 0: g0 = h0_prev @ Uh0^T + x_t @ Wx0^T
        layer_step(d_h0T[rd], d_xT + t * (INP * Bb),
                   Uh0, Hh, Hh, Wx0, INP, INP,
                   d_h0T[wr], c0, bg0, bif0, sA, sW);
        grid_barrier(2 * t + 1);
        // layer 1: g1 = h0_new @ Wx1^T + h1_prev @ Uh1^T
        layer_step(d_h0T[wr], d_h1T[rd],
                   Wx1, Hh, Hh, Uh1, Hh, Hh,
                   d_h1T[wr], c1, bg1, bif1, sA, sW);
        grid_barrier(2 * t + 2);
    }
}

// ---------------- final fc head: out[b] = h1_final . fcW + fcb ----------------
__global__ void fc_kernel(const float* __restrict__ fcW,
                          const float* __restrict__ fcb,
                          float* __restrict__ out)
{
    int b = threadIdx.x; // 128
    float s = fcb[0];
    const float* h = d_h1T[0]; // t=511: rd=1, wr=0 -> final h1 in buffer 0
    for (int jj = 0; jj < Hh; ++jj)
        s += h[jj * Bb + b] * fcW[jj];
    out[b] = s;
}

// ---------------- launch (4 graph nodes) ----------------
extern "C" void kernel_launch(void* const* d_in, const int* in_sizes, int n_in,
                              void* d_out, int out_size)
{
    const float* x        = (const float*)d_in[0];
    const float* boundary = (const float*)d_in[1];
    const float* Wx0      = (const float*)d_in[2];
    const float* bx0      = (const float*)d_in[3];
    const float* Uh0      = (const float*)d_in[4];
    const float* bh0      = (const float*)d_in[5];
    const float* Wb0      = (const float*)d_in[6];
    const float* bb0      = (const float*)d_in[7];
    const float* Wx1      = (const float*)d_in[8];
    const float* bx1      = (const float*)d_in[9];
    const float* Uh1      = (const float*)d_in[10];
    const float* bh1      = (const float*)d_in[11];
    const float* Wb1      = (const float*)d_in[12];
    const float* bb1      = (const float*)d_in[13];
    const float* fcW      = (const float*)d_in[14];
    const float* fcb      = (const float*)d_in[15];
    float* out            = (float*)d_out;

    setup_kernel<<<(Bb * Hh) / 256, 256>>>(boundary, bx0, bh0, bb0, Wb0,
                                           bx1, bh1, bb1, Wb1);
    transpose_kernel<<<(Tt * INP * Bb) / 256, 256>>>(x);
    lstm_persistent<<<NBLK, NTHR>>>(Uh0, Wx0, Wx1, Uh1);
    fc_kernel<<<1, 128>>>(fcW, fcb, out);
}

// round 5
// speedup vs baseline: 3.5629x; 3.5629x over previous
#include <cuda_runtime.h>
#include <cuda_bf16.h>
#include <math.h>
#include <stdint.h>

// CustomLSTM: 2-layer LSTM, B=128, T=512, IN=64, H=1024, OUT=1
// Round 5: persistent kernel using classic mma.sync bf16 (m16n8k16, fp32 acc),
// 3-term hi/lo split for fp32-grade accuracy. cp.async double-buffered staging.
// (tcgen05 is unavailable: harness compiles via compute_103 PTX, not sm_103a.)

#define Bb    128
#define Tt    512
#define INP   64
#define Hh    1024
#define NBLK  128
#define NTHR  256

typedef unsigned int u32;
typedef unsigned short us;
typedef unsigned long long u64;

// ---- smem layout (us = 2-byte units) ----
// stage: ActH[128][72] ActL[128][72] WH[32][72] WL[32][72]  (rows padded to 144B)
#define ACT_PL   9216u            // 128*72 us
#define W_PL     2304u            // 32*72 us
#define STG_US   (2*ACT_PL + 2*W_PL)     // 23040 us per stage
#define SGATE_US (2u*STG_US)             // 46080: float gate buffer [32][132]
#define HSTG_US  (SGATE_US + 8448u)      // 54528: h staging, 2048 us
#define DYN_SMEM ((HSTG_US + 2048u) * 2u + 512u)   // bytes

// ---------------- device scratch ----------------
__device__ __align__(128) us d_h0[2][2][Bb][Hh];   // [buf][plane hi/lo][b][k]
__device__ __align__(128) us d_h1[2][2][Bb][Hh];
__device__ __align__(128) us d_x[Tt][2][Bb][INP];  // [t][plane][b][k]
__device__ __align__(128) us d_w[128u * 49u * 2u * 32u * 64u]; // [cta][chunk][plane][32][64]
__device__ float d_bias0[4096], d_bias1[4096];
__device__ float d_bi0[Bb * Hh], d_bi1[Bb * Hh];
__device__ float d_h1f[Bb * Hh];
__device__ u32 g_count;
__device__ volatile u32 g_gen;
__device__ volatile u32 g_abort;

// ---------------- helpers ----------------
__device__ __forceinline__ u32 smem_u32(const void* p) {
    u32 a; asm("{ .reg .u64 t; cvta.to.shared.u64 t, %1; cvt.u32.u64 %0, t; }" : "=r"(a) : "l"(p));
    return a;
}
__device__ __forceinline__ void cpa16(u32 dst, const void* src) {
    asm volatile("cp.async.cg.shared.global [%0], [%1], 16;" :: "r"(dst), "l"(src));
}
#define CP_COMMIT() asm volatile("cp.async.commit_group;" ::: "memory")
#define CP_WAIT(n)  asm volatile("cp.async.wait_group %0;" :: "n"(n) : "memory")

__device__ __forceinline__ void mma16816(float* c, const u32* a, u32 b0, u32 b1) {
    asm volatile("mma.sync.aligned.m16n8k16.row.col.f32.bf16.bf16.f32 "
                 "{%0,%1,%2,%3}, {%4,%5,%6,%7}, {%8,%9}, {%0,%1,%2,%3};"
                 : "+f"(c[0]), "+f"(c[1]), "+f"(c[2]), "+f"(c[3])
                 : "r"(a[0]), "r"(a[1]), "r"(a[2]), "r"(a[3]), "r"(b0), "r"(b1));
}

__device__ __forceinline__ float sigf(float x) { return __fdividef(1.f, 1.f + __expf(-x)); }
__device__ __forceinline__ float tanh_f(float x) {
    float xc = fminf(fmaxf(x, -15.f), 15.f);
    float e  = __expf(-2.f * xc);
    return (1.f - e) * __fdividef(1.f, 1.f + e);
}
__device__ __forceinline__ void bsplit(float v, us& hi, us& lo) {
    __nv_bfloat16 h = __float2bfloat16_rn(v);
    __nv_bfloat16 l = __float2bfloat16_rn(v - __bfloat162float(h));
    hi = __bfloat16_as_ushort(h); lo = __bfloat16_as_ushort(l);
}

// ---------------- setup kernels ----------------
__global__ void setup_misc(const float* __restrict__ boundary,
                           const float* __restrict__ bx0, const float* __restrict__ bh0,
                           const float* __restrict__ bb0, const float* __restrict__ Wb0,
                           const float* __restrict__ bx1, const float* __restrict__ bh1,
                           const float* __restrict__ bb1, const float* __restrict__ Wb1)
{
    int idx = blockIdx.x * 256 + threadIdx.x;   // 131072
    if (idx == 0) { g_count = 0; g_gen = 0; g_abort = 0; }
    ((u32*)d_h0)[idx] = 0u;                     // zero buffer 0 (both planes)
    ((u32*)d_h1)[idx] = 0u;
    int b = idx >> 10, j = idx & 1023;
    float p0 = boundary[b * 2 + 0], p1 = boundary[b * 2 + 1];
    d_bi0[idx] = p0 * Wb0[j * 2 + 0] + p1 * Wb0[j * 2 + 1] + bb0[j];
    d_bi1[idx] = p0 * Wb1[j * 2 + 0] + p1 * Wb1[j * 2 + 1] + bb1[j];
    if (idx < 4096) {
        d_bias0[idx] = bx0[idx] + bh0[idx];
        d_bias1[idx] = bx1[idx] + bh1[idx];
    }
}

__global__ void setup_x(const float* __restrict__ x)
{
    int idx = blockIdx.x * 256 + threadIdx.x;   // 4194304
    int k = idx & 63, b = (idx >> 6) & 127, t = idx >> 13;
    float v = x[b * (Tt * INP) + t * INP + k];
    us hi, lo; bsplit(v, hi, lo);
    d_x[t][0][b][k] = hi;
    d_x[t][1][b][k] = lo;
}

__global__ void repack_w(const float* __restrict__ Uh0, const float* __restrict__ Wx0,
                         const float* __restrict__ Wx1, const float* __restrict__ Uh1)
{
    int idx = blockIdx.x * 256 + threadIdx.x;   // 128*49*32*64 = 12845056
    int k   = idx & 63;
    int r   = (idx >> 6) & 31;
    int w   = (idx >> 11) % 49;
    int cta = idx / (49 << 11);
    int g = r >> 3, u = r & 7;
    int grow = g * Hh + cta * 8 + u;
    float wv;
    if (w < 16)       wv = Uh0[grow * Hh + w * 64 + k];
    else if (w == 16) wv = Wx0[grow * INP + k];
    else if (w < 33)  wv = Wx1[grow * Hh + (w - 17) * 64 + k];
    else              wv = Uh1[grow * Hh + (w - 33) * 64 + k];
    us hi, lo; bsplit(wv, hi, lo);
    u64 base = ((u64)(cta * 49 + w)) * 2u * 2048u;
    d_w[base + 0    + r * 64 + k] = hi;
    d_w[base + 2048 + r * 64 + k] = lo;
}

// ---------------- grid barrier (bounded, abort-safe) ----------------
__device__ __forceinline__ void grid_barrier(u32 target)
{
    __threadfence();
    __syncthreads();
    if (threadIdx.x == 0) {
        u32 old = atomicAdd(&g_count, 1u);
        if (old == NBLK - 1) {
            g_count = 0;
            __threadfence();
            g_gen = target;
        } else {
            u32 i = 0;
            while (g_gen < target) {
                __nanosleep(64);
                if (g_abort) break;
                if (++i > (1u << 24)) { g_abort = 1u; break; }
            }
        }
    }
    __syncthreads();
}

// ---------------- chunk staging ----------------
__device__ __forceinline__ void load_chunk(us* S, u32 Sa, int w, int t, int cta, int tid)
{
    int rd = t & 1, wr = rd ^ 1;
    const us* aH; const us* aL; int K;
    if (w < 16)      { aH = &d_h0[rd][0][0][w * 64];        aL = &d_h0[rd][1][0][w * 64];        K = Hh; }
    else if (w == 16){ aH = &d_x[t][0][0][0];               aL = &d_x[t][1][0][0];               K = INP; }
    else if (w < 33) { aH = &d_h0[wr][0][0][(w - 17) * 64]; aL = &d_h0[wr][1][0][(w - 17) * 64]; K = Hh; }
    else             { aH = &d_h1[rd][0][0][(w - 33) * 64]; aL = &d_h1[rd][1][0][(w - 33) * 64]; K = Hh; }

#pragma unroll
    for (int i = 0; i < 4; ++i) {               // ActH: 1024 x 16B
        int idx = tid + i * 256;
        int row = idx >> 3, seg = idx & 7;
        cpa16(Sa + (row * 72 + seg * 8) * 2, aH + row * K + seg * 8);
    }
#pragma unroll
    for (int i = 0; i < 4; ++i) {               // ActL
        int idx = tid + i * 256;
        int row = idx >> 3, seg = idx & 7;
        cpa16(Sa + (ACT_PL + row * 72 + seg * 8) * 2, aL + row * K + seg * 8);
    }
    const us* wsrc = d_w + ((u64)(cta * 49 + w)) * 2u * 2048u;
#pragma unroll
    for (int i = 0; i < 2; ++i) {               // W hi+lo: 512 x 16B
        int idx = tid + i * 256;
        int pl = idx >> 8, row = (idx >> 3) & 31, seg = idx & 7;
        cpa16(Sa + (2 * ACT_PL + pl * W_PL + row * 72 + seg * 8) * 2,
              wsrc + pl * 2048 + row * 64 + seg * 8);
    }
}

// ---------------- GEMM over one 64-K chunk ----------------
__device__ __forceinline__ void compute_chunk(const us* S, int mrow, int wcol,
                                              int lane, float acc[4][4])
{
    const us* ActH = S;
    const us* ActL = S + ACT_PL;
    const us* WH   = S + 2 * ACT_PL;
    const us* WL   = S + 2 * ACT_PL + W_PL;
    const int r0   = mrow * 16 + (lane >> 2);
    const int tg2  = (lane & 3) * 2;
    const int col0 = wcol * 32 + (lane >> 2);
#pragma unroll
    for (int kk = 0; kk < 64; kk += 16) {
        const int ka = kk + tg2;
        u32 wh[4], wl[4];
        wh[0] = *(const u32*)(WH + r0 * 72 + ka);
        wh[1] = *(const u32*)(WH + (r0 + 8) * 72 + ka);
        wh[2] = *(const u32*)(WH + r0 * 72 + ka + 8);
        wh[3] = *(const u32*)(WH + (r0 + 8) * 72 + ka + 8);
        wl[0] = *(const u32*)(WL + r0 * 72 + ka);
        wl[1] = *(const u32*)(WL + (r0 + 8) * 72 + ka);
        wl[2] = *(const u32*)(WL + r0 * 72 + ka + 8);
        wl[3] = *(const u32*)(WL + (r0 + 8) * 72 + ka + 8);
#pragma unroll
        for (int nt = 0; nt < 4; ++nt) {
            const int c = (col0 + nt * 8) * 72 + ka;
            u32 bh0 = *(const u32*)(ActH + c);
            u32 bh1 = *(const u32*)(ActH + c + 8);
            u32 bl0 = *(const u32*)(ActL + c);
            u32 bl1 = *(const u32*)(ActL + c + 8);
            mma16816(acc[nt], wh, bh0, bh1);   // hi x hi
            mma16816(acc[nt], wl, bh0, bh1);   // w_lo x a_hi
            mma16816(acc[nt], wh, bl0, bl1);   // w_hi x a_lo
        }
    }
}

// ---------------- persistent LSTM kernel ----------------
__global__ void __launch_bounds__(NTHR, 1) lstm_mma()
{
    extern __shared__ __align__(16) us sm[];
    const int tid  = threadIdx.x;
    const int cta  = blockIdx.x;
    const int lane = tid & 31;
    const int wid  = tid >> 5;
    const int mrow = wid & 1;          // M-tile (rows 0-15 / 16-31)
    const int wcol = wid >> 1;         // batch column (x32)
    const u32 smA  = smem_u32(sm);

    float* sgate = (float*)(sm + SGATE_US);   // [32][132]
    us*    hstg  = sm + HSTG_US;              // [2 plane][128 b][8 u]... stored [pl*1024 + b*8 + u]

    // per-thread cell ownership: unit u = wid, batches b = lane + 32p
    const int j = cta * 8 + wid;
    float bg0[4], bg1[4], bif0[4], bif1[4];
#pragma unroll
    for (int g = 0; g < 4; ++g) {
        bg0[g] = d_bias0[g * Hh + j];
        bg1[g] = d_bias1[g * Hh + j];
    }
#pragma unroll
    for (int p = 0; p < 4; ++p) {
        bif0[p] = d_bi0[(lane + 32 * p) * Hh + j];
        bif1[p] = d_bi1[(lane + 32 * p) * Hh + j];
    }
    float c0[4] = {0.f, 0.f, 0.f, 0.f};
    float c1[4] = {0.f, 0.f, 0.f, 0.f};

    for (int t = 0; t < Tt && !g_abort; ++t) {
        const int wr = (t & 1) ^ 1;
#pragma unroll 1
        for (int layer = 0; layer < 2; ++layer) {
            const int wbeg = layer ? 17 : 0;
            const int nc   = layer ? 32 : 17;

            float acc[4][4];
#pragma unroll
            for (int nt = 0; nt < 4; ++nt)
#pragma unroll
                for (int q = 0; q < 4; ++q) acc[nt][q] = 0.f;

            load_chunk(sm, smA, wbeg, t, cta, tid);
            CP_COMMIT();
#pragma unroll 1
            for (int ci = 0; ci < nc; ++ci) {
                const int s = ci & 1;
                if (ci + 1 < nc) {
                    load_chunk(sm + ((ci + 1) & 1) * STG_US,
                               smA + (((ci + 1) & 1) * STG_US) * 2,
                               wbeg + ci + 1, t, cta, tid);
                    CP_COMMIT();
                    CP_WAIT(1);
                } else {
                    CP_WAIT(0);
                }
                __syncthreads();
                compute_chunk(sm + s * STG_US, mrow, wcol, lane, acc);
                __syncthreads();
            }

            // ---- epilogue: D -> sgate ----
            {
                const int row = mrow * 16 + (lane >> 2);
                const int col = wcol * 32 + (lane & 3) * 2;
#pragma unroll
                for (int nt = 0; nt < 4; ++nt) {
                    const int cbase = col + nt * 8;
                    sgate[row * 132 + cbase]           = acc[nt][0];
                    sgate[row * 132 + cbase + 1]       = acc[nt][1];
                    sgate[(row + 8) * 132 + cbase]     = acc[nt][2];
                    sgate[(row + 8) * 132 + cbase + 1] = acc[nt][3];
                }
            }
            __syncthreads();

            // ---- cell: unit wid, batches lane+32p ----
            {
                const float* bg  = layer ? bg1 : bg0;
                const float* bif = layer ? bif1 : bif0;
                float* cc = layer ? c1 : c0;
#pragma unroll
                for (int p = 0; p < 4; ++p) {
                    const int b = lane + 32 * p;
                    float pi = sgate[(0  + wid) * 132 + b] + bg[0];
                    float pf = sgate[(8  + wid) * 132 + b] + bg[1] + bif[p];
                    float po = sgate[(16 + wid) * 132 + b] + bg[2];
                    float pg = sgate[(24 + wid) * 132 + b] + bg[3];
                    float iv = sigf(pi), fv = sigf(pf), ov = sigf(po), gg = tanh_f(pg);
                    float cn = fv * cc[p] + iv * gg;
                    cc[p] = cn;
                    float hv = ov * tanh_f(cn);
                    us hi, lo; bsplit(hv, hi, lo);
                    hstg[b * 8 + wid]        = hi;
                    hstg[1024 + b * 8 + wid] = lo;
                    if (layer == 1 && t == Tt - 1)
                        d_h1f[b * Hh + j] = hv;
                }
            }
            __syncthreads();

            // ---- coalesced h writeback: 16B per (plane, b) ----
            {
                const int pl = tid >> 7, b = tid & 127;
                uint4 v = *(const uint4*)(hstg + pl * 1024 + b * 8);
                us* dst = (layer ? &d_h1[wr][pl][b][cta * 8]
                                 : &d_h0[wr][pl][b][cta * 8]);
                *(uint4*)dst = v;
            }

            grid_barrier(2 * t + layer + 1);
            if (g_abort) break;
        }
    }
}

// ---------------- fc head ----------------
__global__ void fc_kernel(const float* __restrict__ fcW,
                          const float* __restrict__ fcb,
                          float* __restrict__ out)
{
    __shared__ float red[256];
    int b = blockIdx.x, tid = threadIdx.x;
    float s = 0.f;
    for (int jj = tid; jj < Hh; jj += 256) s += d_h1f[b * Hh + jj] * fcW[jj];
    red[tid] = s;
    __syncthreads();
    for (int o = 128; o > 0; o >>= 1) {
        if (tid < o) red[tid] += red[tid + o];
        __syncthreads();
    }
    if (tid == 0) out[b] = red[0] + fcb[0];
}

// ---------------- launch (5 graph nodes) ----------------
extern "C" void kernel_launch(void* const* d_in, const int* in_sizes, int n_in,
                              void* d_out, int out_size)
{
    const float* x        = (const float*)d_in[0];
    const float* boundary = (const float*)d_in[1];
    const float* Wx0      = (const float*)d_in[2];
    const float* bx0      = (const float*)d_in[3];
    const float* Uh0      = (const float*)d_in[4];
    const float* bh0      = (const float*)d_in[5];
    const float* Wb0      = (const float*)d_in[6];
    const float* bb0      = (const float*)d_in[7];
    const float* Wx1      = (const float*)d_in[8];
    const float* bx1      = (const float*)d_in[9];
    const float* Uh1      = (const float*)d_in[10];
    const float* bh1      = (const float*)d_in[11];
    const float* Wb1      = (const float*)d_in[12];
    const float* bb1      = (const float*)d_in[13];
    const float* fcW      = (const float*)d_in[14];
    const float* fcb      = (const float*)d_in[15];
    float* out            = (float*)d_out;

    cudaFuncSetAttribute(lstm_mma, cudaFuncAttributeMaxDynamicSharedMemorySize, DYN_SMEM);

    setup_misc<<<(Bb * Hh) / 256, 256>>>(boundary, bx0, bh0, bb0, Wb0, bx1, bh1, bb1, Wb1);
    setup_x<<<(Tt * Bb * INP) / 256, 256>>>(x);
    repack_w<<<(128 * 49 * 32 * 64) / 256, 256>>>(Uh0, Wx0, Wx1, Uh1);
    lstm_mma<<<NBLK, NTHR, DYN_SMEM>>>();
    fc_kernel<<<Bb, 256>>>(fcW, fcb, out);
}

// round 6
// speedup vs baseline: 4.1252x; 1.1578x over previous
#include <cuda_runtime.h>
#include <cuda_bf16.h>
#include <math.h>
#include <stdint.h>

// CustomLSTM: 2-layer LSTM, B=128, T=512, IN=64, H=1024, OUT=1
// Round 6: mma.sync bf16 3-term split + ldmatrix fragments + 3-stage cp.async
// pipeline (1 syncthreads/chunk) + 1 grid barrier per step.

#define Bb    128
#define Tt    512
#define INP   64
#define Hh    1024
#define NBLK  128
#define NTHR  256

typedef unsigned int u32;
typedef unsigned short us;
typedef unsigned long long u64;

// ---- smem layout (us = 2-byte units) ----
// stage: ActH[128][72] ActL[128][72] WH[32][72] WL[32][72]
#define ACT_PL   9216u              // 128*72 us
#define W_PL     2304u              // 32*72 us
#define STG_US   (2*ACT_PL + 2*W_PL)       // 23040 us / stage
#define NSTG     3
#define SGATE_US (NSTG * STG_US)           // float gate buffer [32][132]
#define HSTG_US  (SGATE_US + 8448u)        // h staging (2048 us)
#define DYN_SMEM ((HSTG_US + 2048u) * 2u)  // bytes = 159232

// ---------------- device scratch ----------------
__device__ __align__(128) us d_h0[2][2][Bb][Hh];   // [buf][plane][b][k]
__device__ __align__(128) us d_h1[2][2][Bb][Hh];
__device__ __align__(128) us d_x[Tt][2][Bb][INP];
__device__ __align__(128) us d_w[128u * 49u * 2u * 32u * 64u];
__device__ float d_bias0[4096], d_bias1[4096];
__device__ float d_bi0[Bb * Hh], d_bi1[Bb * Hh];
__device__ float d_h1f[Bb * Hh];
__device__ u32 g_count;
__device__ volatile u32 g_gen;
__device__ volatile u32 g_abort;

// ---------------- helpers ----------------
__device__ __forceinline__ u32 smem_u32(const void* p) {
    u32 a; asm("{ .reg .u64 t; cvta.to.shared.u64 t, %1; cvt.u32.u64 %0, t; }" : "=r"(a) : "l"(p));
    return a;
}
__device__ __forceinline__ void cpa16(u32 dst, const void* src) {
    asm volatile("cp.async.cg.shared.global [%0], [%1], 16;" :: "r"(dst), "l"(src));
}
#define CP_COMMIT() asm volatile("cp.async.commit_group;" ::: "memory")
#define CP_WAIT0()  asm volatile("cp.async.wait_group 0;" ::: "memory")
#define CP_WAIT1()  asm volatile("cp.async.wait_group 1;" ::: "memory")

__device__ __forceinline__ void ldsm4(u32* r, u32 addr) {
    asm volatile("ldmatrix.sync.aligned.m8n8.x4.shared.b16 {%0,%1,%2,%3}, [%4];"
                 : "=r"(r[0]), "=r"(r[1]), "=r"(r[2]), "=r"(r[3]) : "r"(addr));
}
__device__ __forceinline__ void mma16816(float* c, const u32* a, u32 b0, u32 b1) {
    asm volatile("mma.sync.aligned.m16n8k16.row.col.f32.bf16.bf16.f32 "
                 "{%0,%1,%2,%3}, {%4,%5,%6,%7}, {%8,%9}, {%0,%1,%2,%3};"
                 : "+f"(c[0]), "+f"(c[1]), "+f"(c[2]), "+f"(c[3])
                 : "r"(a[0]), "r"(a[1]), "r"(a[2]), "r"(a[3]), "r"(b0), "r"(b1));
}

__device__ __forceinline__ float sigf(float x) { return __fdividef(1.f, 1.f + __expf(-x)); }
__device__ __forceinline__ float tanh_f(float x) {
    float xc = fminf(fmaxf(x, -15.f), 15.f);
    float e  = __expf(-2.f * xc);
    return (1.f - e) * __fdividef(1.f, 1.f + e);
}
__device__ __forceinline__ void bsplit(float v, us& hi, us& lo) {
    __nv_bfloat16 h = __float2bfloat16_rn(v);
    __nv_bfloat16 l = __float2bfloat16_rn(v - __bfloat162float(h));
    hi = __bfloat16_as_ushort(h); lo = __bfloat16_as_ushort(l);
}

// ---------------- setup kernels ----------------
__global__ void setup_misc(const float* __restrict__ boundary,
                           const float* __restrict__ bx0, const float* __restrict__ bh0,
                           const float* __restrict__ bb0, const float* __restrict__ Wb0,
                           const float* __restrict__ bx1, const float* __restrict__ bh1,
                           const float* __restrict__ bb1, const float* __restrict__ Wb1)
{
    int idx = blockIdx.x * 256 + threadIdx.x;   // 131072
    if (idx == 0) { g_count = 0; g_gen = 0; g_abort = 0; }
    ((u32*)d_h0)[idx] = 0u;
    ((u32*)d_h1)[idx] = 0u;
    int b = idx >> 10, j = idx & 1023;
    float p0 = boundary[b * 2 + 0], p1 = boundary[b * 2 + 1];
    d_bi0[idx] = p0 * Wb0[j * 2 + 0] + p1 * Wb0[j * 2 + 1] + bb0[j];
    d_bi1[idx] = p0 * Wb1[j * 2 + 0] + p1 * Wb1[j * 2 + 1] + bb1[j];
    if (idx < 4096) {
        d_bias0[idx] = bx0[idx] + bh0[idx];
        d_bias1[idx] = bx1[idx] + bh1[idx];
    }
}

__global__ void setup_x(const float* __restrict__ x)
{
    int idx = blockIdx.x * 256 + threadIdx.x;   // 4194304
    int k = idx & 63, b = (idx >> 6) & 127, t = idx >> 13;
    float v = x[b * (Tt * INP) + t * INP + k];
    us hi, lo; bsplit(v, hi, lo);
    d_x[t][0][b][k] = hi;
    d_x[t][1][b][k] = lo;
}

__global__ void repack_w(const float* __restrict__ Uh0, const float* __restrict__ Wx0,
                         const float* __restrict__ Wx1, const float* __restrict__ Uh1)
{
    int idx = blockIdx.x * 256 + threadIdx.x;   // 12845056
    int k   = idx & 63;
    int r   = (idx >> 6) & 31;
    int w   = (idx >> 11) % 49;
    int cta = idx / (49 << 11);
    int g = r >> 3, u = r & 7;
    int grow = g * Hh + cta * 8 + u;
    float wv;
    if (w < 16)       wv = Uh0[grow * Hh + w * 64 + k];
    else if (w == 16) wv = Wx0[grow * INP + k];
    else if (w < 33)  wv = Wx1[grow * Hh + (w - 17) * 64 + k];
    else              wv = Uh1[grow * Hh + (w - 33) * 64 + k];
    us hi, lo; bsplit(wv, hi, lo);
    u64 base = ((u64)(cta * 49 + w)) * 2u * 2048u;
    d_w[base + 0    + r * 64 + k] = hi;
    d_w[base + 2048 + r * 64 + k] = lo;
}

// ---------------- grid barrier (bounded, abort-safe) ----------------
__device__ __forceinline__ void grid_barrier(u32 target)
{
    __threadfence();
    __syncthreads();
    if (threadIdx.x == 0) {
        u32 old = atomicAdd(&g_count, 1u);
        if (old == NBLK - 1) {
            g_count = 0;
            __threadfence();
            g_gen = target;
        } else {
            u32 i = 0;
            while (g_gen < target) {
                __nanosleep(64);
                if (g_abort) break;
                if (++i > (1u << 24)) { g_abort = 1u; break; }
            }
        }
    }
    __syncthreads();
}

// ---------------- chunk staging ----------------
__device__ __forceinline__ void load_chunk(u32 Sa, int w, int t, int cta, int tid)
{
    int rd = t & 1, wr = rd ^ 1;
    const us* aH; const us* aL; int K;
    if (w < 16)      { aH = &d_h0[rd][0][0][w * 64];        aL = &d_h0[rd][1][0][w * 64];        K = Hh; }
    else if (w == 16){ aH = &d_x[t][0][0][0];               aL = &d_x[t][1][0][0];               K = INP; }
    else if (w < 33) { aH = &d_h0[wr][0][0][(w - 17) * 64]; aL = &d_h0[wr][1][0][(w - 17) * 64]; K = Hh; }
    else             { aH = &d_h1[rd][0][0][(w - 33) * 64]; aL = &d_h1[rd][1][0][(w - 33) * 64]; K = Hh; }

#pragma unroll
    for (int i = 0; i < 4; ++i) {               // ActH
        int idx = tid + i * 256;
        int row = idx >> 3, seg = idx & 7;
        cpa16(Sa + (row * 72 + seg * 8) * 2, aH + row * K + seg * 8);
    }
#pragma unroll
    for (int i = 0; i < 4; ++i) {               // ActL
        int idx = tid + i * 256;
        int row = idx >> 3, seg = idx & 7;
        cpa16(Sa + (ACT_PL + row * 72 + seg * 8) * 2, aL + row * K + seg * 8);
    }
    const us* wsrc = d_w + ((u64)(cta * 49 + w)) * 2u * 2048u;
#pragma unroll
    for (int i = 0; i < 2; ++i) {               // W hi+lo
        int idx = tid + i * 256;
        int pl = idx >> 8, row = (idx >> 3) & 31, seg = idx & 7;
        cpa16(Sa + (2 * ACT_PL + pl * W_PL + row * 72 + seg * 8) * 2,
              wsrc + pl * 2048 + row * 64 + seg * 8);
    }
}

// ---------------- persistent LSTM kernel ----------------
__global__ void __launch_bounds__(NTHR, 1) lstm_mma()
{
    extern __shared__ __align__(16) us sm[];
    const int tid  = threadIdx.x;
    const int cta  = blockIdx.x;
    const int lane = tid & 31;
    const int wid  = tid >> 5;
    const int mrow = wid & 1;
    const int wcol = wid >> 1;
    const u32 smA  = smem_u32(sm);

    float* sgate = (float*)(sm + SGATE_US);
    us*    hstg  = sm + HSTG_US;

    // ldmatrix per-lane source offsets (us units within a stage)
    const u32 aoff = (u32)((mrow * 16 + (lane & 15)) * 72 + ((lane >> 4) * 8));
    const u32 boffA = (u32)((wcol * 32 + (lane & 7) + ((lane >> 4) & 1) * 8) * 72
                            + (((lane >> 3) & 1) * 8));
    const u32 boffB = boffA + 16 * 72;

    const int j = cta * 8 + wid;
    float bg0[4], bg1[4], bif0[4], bif1[4];
#pragma unroll
    for (int g = 0; g < 4; ++g) {
        bg0[g] = d_bias0[g * Hh + j];
        bg1[g] = d_bias1[g * Hh + j];
    }
#pragma unroll
    for (int p = 0; p < 4; ++p) {
        bif0[p] = d_bi0[(lane + 32 * p) * Hh + j];
        bif1[p] = d_bi1[(lane + 32 * p) * Hh + j];
    }
    float c0[4] = {0.f, 0.f, 0.f, 0.f};
    float c1[4] = {0.f, 0.f, 0.f, 0.f};

    for (int t = 0; t < Tt && !g_abort; ++t) {
        const int wr = (t & 1) ^ 1;
#pragma unroll 1
        for (int layer = 0; layer < 2; ++layer) {
            const int wbeg = layer ? 17 : 0;
            const int nc   = layer ? 32 : 17;

            float acc[4][4];
#pragma unroll
            for (int nt = 0; nt < 4; ++nt)
#pragma unroll
                for (int q = 0; q < 4; ++q) acc[nt][q] = 0.f;

            // prologue: 2 chunks in flight
            load_chunk(smA, wbeg, t, cta, tid);
            CP_COMMIT();
            if (nc > 1) {
                load_chunk(smA + STG_US * 2, wbeg + 1, t, cta, tid);
                CP_COMMIT();
            }

#pragma unroll 1
            for (int ci = 0; ci < nc; ++ci) {
                if (ci + 1 < nc) CP_WAIT1(); else CP_WAIT0();
                __syncthreads();

                const u32 SaB  = smA + (u32)(ci % NSTG) * (STG_US * 2);
                const u32 actH = SaB;
                const u32 actL = SaB + ACT_PL * 2;
                const u32 whB  = SaB + (2 * ACT_PL) * 2;
                const u32 wlB  = SaB + (2 * ACT_PL + W_PL) * 2;
#pragma unroll
                for (int kk = 0; kk < 64; kk += 16) {
                    const u32 k2 = (u32)kk * 2;
                    u32 wh[4], wl[4], bh1[4], bh2[4], bl1[4], bl2[4];
                    ldsm4(wh,  whB  + aoff * 2 + k2);
                    ldsm4(wl,  wlB  + aoff * 2 + k2);
                    ldsm4(bh1, actH + boffA * 2 + k2);
                    ldsm4(bh2, actH + boffB * 2 + k2);
                    ldsm4(bl1, actL + boffA * 2 + k2);
                    ldsm4(bl2, actL + boffB * 2 + k2);

                    mma16816(acc[0], wh, bh1[0], bh1[1]);
                    mma16816(acc[1], wh, bh1[2], bh1[3]);
                    mma16816(acc[2], wh, bh2[0], bh2[1]);
                    mma16816(acc[3], wh, bh2[2], bh2[3]);
                    mma16816(acc[0], wl, bh1[0], bh1[1]);
                    mma16816(acc[1], wl, bh1[2], bh1[3]);
                    mma16816(acc[2], wl, bh2[0], bh2[1]);
                    mma16816(acc[3], wl, bh2[2], bh2[3]);
                    mma16816(acc[0], wh, bl1[0], bl1[1]);
                    mma16816(acc[1], wh, bl1[2], bl1[3]);
                    mma16816(acc[2], wh, bl2[0], bl2[1]);
                    mma16816(acc[3], wh, bl2[2], bl2[3]);
                }

                if (ci + 2 < nc) {
                    load_chunk(smA + (u32)((ci + 2) % NSTG) * (STG_US * 2),
                               wbeg + ci + 2, t, cta, tid);
                    CP_COMMIT();
                }
            }

            // ---- epilogue: acc -> sgate ----
            {
                const int row = mrow * 16 + (lane >> 2);
                const int col = wcol * 32 + (lane & 3) * 2;
#pragma unroll
                for (int nt = 0; nt < 4; ++nt) {
                    const int cbase = col + nt * 8;
                    sgate[row * 132 + cbase]           = acc[nt][0];
                    sgate[row * 132 + cbase + 1]       = acc[nt][1];
                    sgate[(row + 8) * 132 + cbase]     = acc[nt][2];
                    sgate[(row + 8) * 132 + cbase + 1] = acc[nt][3];
                }
            }
            __syncthreads();

            // ---- cell: unit wid, batches lane+32p ----
            {
                const float* bg  = layer ? bg1 : bg0;
                const float* bif = layer ? bif1 : bif0;
                float* cc = layer ? c1 : c0;
#pragma unroll
                for (int p = 0; p < 4; ++p) {
                    const int b = lane + 32 * p;
                    float pi = sgate[(0  + wid) * 132 + b] + bg[0];
                    float pf = sgate[(8  + wid) * 132 + b] + bg[1] + bif[p];
                    float po = sgate[(16 + wid) * 132 + b] + bg[2];
                    float pg = sgate[(24 + wid) * 132 + b] + bg[3];
                    float iv = sigf(pi), fv = sigf(pf), ov = sigf(po), gg = tanh_f(pg);
                    float cn = fv * cc[p] + iv * gg;
                    cc[p] = cn;
                    float hv = ov * tanh_f(cn);
                    us hi, lo; bsplit(hv, hi, lo);
                    hstg[b * 8 + wid]        = hi;
                    hstg[1024 + b * 8 + wid] = lo;
                    if (layer == 1 && t == Tt - 1)
                        d_h1f[b * Hh + j] = hv;
                }
            }
            __syncthreads();

            // ---- coalesced h writeback ----
            {
                const int pl = tid >> 7, b = tid & 127;
                uint4 v = *(const uint4*)(hstg + pl * 1024 + b * 8);
                us* dst = (layer ? &d_h1[wr][pl][b][cta * 8]
                                 : &d_h0[wr][pl][b][cta * 8]);
                *(uint4*)dst = v;
            }

            if (layer == 0) {
                grid_barrier(t + 1);     // single barrier per step
                if (g_abort) break;
            } else {
                __syncthreads();         // protect hstg reuse within CTA
            }
        }
    }
}

// ---------------- fc head ----------------
__global__ void fc_kernel(const float* __restrict__ fcW,
                          const float* __restrict__ fcb,
                          float* __restrict__ out)
{
    __shared__ float red[256];
    int b = blockIdx.x, tid = threadIdx.x;
    float s = 0.f;
    for (int jj = tid; jj < Hh; jj += 256) s += d_h1f[b * Hh + jj] * fcW[jj];
    red[tid] = s;
    __syncthreads();
    for (int o = 128; o > 0; o >>= 1) {
        if (tid < o) red[tid] += red[tid + o];
        __syncthreads();
    }
    if (tid == 0) out[b] = red[0] + fcb[0];
}

// ---------------- launch (5 graph nodes) ----------------
extern "C" void kernel_launch(void* const* d_in, const int* in_sizes, int n_in,
                              void* d_out, int out_size)
{
    const float* x        = (const float*)d_in[0];
    const float* boundary = (const float*)d_in[1];
    const float* Wx0      = (const float*)d_in[2];
    const float* bx0      = (const float*)d_in[3];
    const float* Uh0      = (const float*)d_in[4];
    const float* bh0      = (const float*)d_in[5];
    const float* Wb0      = (const float*)d_in[6];
    const float* bb0      = (const float*)d_in[7];
    const float* Wx1      = (const float*)d_in[8];
    const float* bx1      = (const float*)d_in[9];
    const float* Uh1      = (const float*)d_in[10];
    const float* bh1      = (const float*)d_in[11];
    const float* Wb1      = (const float*)d_in[12];
    const float* bb1      = (const float*)d_in[13];
    const float* fcW      = (const float*)d_in[14];
    const float* fcb      = (const float*)d_in[15];
    float* out            = (float*)d_out;

    cudaFuncSetAttribute(lstm_mma, cudaFuncAttributeMaxDynamicSharedMemorySize, DYN_SMEM);

    setup_misc<<<(Bb * Hh) / 256, 256>>>(boundary, bx0, bh0, bb0, Wb0, bx1, bh1, bb1, Wb1);
    setup_x<<<(Tt * Bb * INP) / 256, 256>>>(x);
    repack_w<<<(128 * 49 * 32 * 64) / 256, 256>>>(Uh0, Wx0, Wx1, Uh1);
    lstm_mma<<<NBLK, NTHR, DYN_SMEM>>>();
    fc_kernel<<<Bb, 256>>>(fcW, fcb, out);
}